// round 1
// baseline (speedup 1.0000x reference)
#include <cuda_runtime.h>
#include <cstdint>

// Volume is 256^3, so (z*H + y)*W + x == (z<<16) | (y<<8) | x when in-bounds.
#define DHW 256

__device__ __forceinline__ float gather(const float* __restrict__ vol,
                                        int z, int y, int x) {
    if ((unsigned)z < (unsigned)DHW &&
        (unsigned)y < (unsigned)DHW &&
        (unsigned)x < (unsigned)DHW) {
        return __ldg(vol + (((z << 8) | y) << 8 | x));
    }
    return 0.0f;
}

__global__ void __launch_bounds__(256)
alpha_grid_mask_kernel(const float4* __restrict__ xyz,
                       const float* __restrict__ vol,
                       const float* __restrict__ aabb,   // [2][3]
                       const int*   __restrict__ cspace, // [1]
                       float* __restrict__ out,
                       int n) {
    int i = blockIdx.x * blockDim.x + threadIdx.x;
    if (i >= n) return;

    // aabb is tiny; these hit L1/L2 and are uniform across the warp.
    float a0x = __ldg(aabb + 0), a0y = __ldg(aabb + 1), a0z = __ldg(aabb + 2);
    float a1x = __ldg(aabb + 3), a1y = __ldg(aabb + 4), a1z = __ldg(aabb + 5);
    float igx = 2.0f / (a1x - a0x);
    float igy = 2.0f / (a1y - a0y);
    float igz = 2.0f / (a1z - a0z);

    float4 p = __ldg(xyz + i);

    float cx = (p.x - a0x) * igx - 1.0f;
    float cy = (p.y - a0y) * igy - 1.0f;
    float cz = (p.z - a0z) * igz - 1.0f;

    if (__ldg(cspace) != 0) {
        float dist = fmaxf(fabsf(cx), fmaxf(fabsf(cy), fabsf(cz))) + 1e-8f;
        float scale = (dist > 1.0f) ? (2.0f - 1.0f / dist) : dist;
        float m = scale * 0.5f / dist;   // scale * 0.5 * (1/dist) applied to coords
        cx *= m; cy *= m; cz *= m;
    }

    // grid x -> W, y -> H, z -> D; align_corners=True
    const float half_span = 0.5f * (DHW - 1);
    float ix = (cx + 1.0f) * half_span;
    float iy = (cy + 1.0f) * half_span;
    float iz = (cz + 1.0f) * half_span;

    float x0f = floorf(ix), y0f = floorf(iy), z0f = floorf(iz);
    float tx = ix - x0f, ty = iy - y0f, tz = iz - z0f;
    int x0 = (int)x0f, y0 = (int)y0f, z0 = (int)z0f;
    int x1 = x0 + 1, y1 = y0 + 1, z1 = z0 + 1;

    // Issue all 8 gathers up front: MLP=8, x-pairs share a 32B sector ~7/8
    // of the time so the +1 load is an L1 hit right after its partner.
    float v000 = gather(vol, z0, y0, x0);
    float v001 = gather(vol, z0, y0, x1);
    float v010 = gather(vol, z0, y1, x0);
    float v011 = gather(vol, z0, y1, x1);
    float v100 = gather(vol, z1, y0, x0);
    float v101 = gather(vol, z1, y0, x1);
    float v110 = gather(vol, z1, y1, x0);
    float v111 = gather(vol, z1, y1, x1);

    float c00 = v000 + tx * (v001 - v000);
    float c01 = v010 + tx * (v011 - v010);
    float c10 = v100 + tx * (v101 - v100);
    float c11 = v110 + tx * (v111 - v110);
    float c0  = c00 + ty * (c01 - c00);
    float c1  = c10 + ty * (c11 - c10);
    out[i] = c0 + tz * (c1 - c0);
}

extern "C" void kernel_launch(void* const* d_in, const int* in_sizes, int n_in,
                              void* d_out, int out_size) {
    const float4* xyz  = (const float4*)d_in[0];   // [N,4] float32
    const float*  vol  = (const float*)d_in[1];    // [256,256,256]
    const float*  aabb = (const float*)d_in[2];    // [2,3]
    const int*    cs   = (const int*)d_in[3];      // [1]
    float* out = (float*)d_out;

    int n = out_size;  // N points
    int threads = 256;
    int blocks = (n + threads - 1) / threads;
    alpha_grid_mask_kernel<<<blocks, threads>>>(xyz, vol, aabb, cs, out, n);
}

// round 2
// speedup vs baseline: 1.0472x; 1.0472x over previous
#include <cuda_runtime.h>
#include <cstdint>

#define DHW 256

// General (padded) gather for the contract_space == 0 fallback path.
__device__ __forceinline__ float gather(const float* __restrict__ vol,
                                        int z, int y, int x) {
    if ((unsigned)z < (unsigned)DHW &&
        (unsigned)y < (unsigned)DHW &&
        (unsigned)x < (unsigned)DHW) {
        return __ldg(vol + (((z << 8) | y) << 8 | x));
    }
    return 0.0f;
}

__global__ void __launch_bounds__(256)
alpha_grid_mask_kernel(const float4* __restrict__ xyz,
                       const float* __restrict__ vol,
                       const float* __restrict__ aabb,   // [2][3]
                       const int*   __restrict__ cspace, // [1]
                       float* __restrict__ out,
                       int n) {
    int i = blockIdx.x * blockDim.x + threadIdx.x;
    if (i >= n) return;

    float a0x = __ldg(aabb + 0), a0y = __ldg(aabb + 1), a0z = __ldg(aabb + 2);
    float a1x = __ldg(aabb + 3), a1y = __ldg(aabb + 4), a1z = __ldg(aabb + 5);
    float igx = 2.0f / (a1x - a0x);
    float igy = 2.0f / (a1y - a0y);
    float igz = 2.0f / (a1z - a0z);

    float4 p = __ldg(xyz + i);

    float cx = (p.x - a0x) * igx - 1.0f;
    float cy = (p.y - a0y) * igy - 1.0f;
    float cz = (p.z - a0z) * igz - 1.0f;

    int cs = __ldg(cspace);
    if (cs != 0) {
        float dist = fmaxf(fabsf(cx), fmaxf(fabsf(cy), fabsf(cz))) + 1e-8f;
        float scale = (dist > 1.0f) ? (2.0f - 1.0f / dist) : dist;
        float m = scale * 0.5f / dist;
        cx *= m; cy *= m; cz *= m;
    }

    const float half_span = 0.5f * (DHW - 1);
    float ix = (cx + 1.0f) * half_span;
    float iy = (cy + 1.0f) * half_span;
    float iz = (cz + 1.0f) * half_span;

    float x0f = floorf(ix), y0f = floorf(iy), z0f = floorf(iz);
    float tx = ix - x0f, ty = iy - y0f, tz = iz - z0f;
    int x0 = (int)x0f, y0 = (int)y0f, z0 = (int)z0f;

    float result;

    if (cs != 0) {
        // Contraction guarantees coords in (-1,1) -> all corners in-bounds.
        // Upper clamps only guard exact-boundary float rounding, where the
        // corresponding lerp weight is exactly 0.
        x0 = min(max(x0, 0), DHW - 1);
        y0 = min(max(y0, 0), DHW - 1);
        z0 = min(max(z0, 0), DHW - 1);
        int x1 = min(x0 + 1, DHW - 1);
        int y1 = min(y0 + 1, DHW - 1);
        int z1 = min(z0 + 1, DHW - 1);

        int b = x0 & ~3;      // 16B-aligned base covering x0..b+3
        int r = x0 & 3;

        const float* r00 = vol + ((((z0 << 8) | y0) << 8) + b);
        const float* r01 = vol + ((((z0 << 8) | y1) << 8) + b);
        const float* r10 = vol + ((((z1 << 8) | y0) << 8) + b);
        const float* r11 = vol + ((((z1 << 8) | y1) << 8) + b);

        // 4 aligned float4 gathers, issued back-to-back for MLP.
        float4 q00 = __ldg((const float4*)r00);
        float4 q01 = __ldg((const float4*)r01);
        float4 q10 = __ldg((const float4*)r10);
        float4 q11 = __ldg((const float4*)r11);

        // Fixup scalar loads only when the x-pair straddles the float4
        // (r == 3): quarter of lanes active -> ~8 wavefronts per LDG.
        float s00 = 0.f, s01 = 0.f, s10 = 0.f, s11 = 0.f;
        if (r == 3) {
            int off = x1 - b;   // = 4 unless clamped at the boundary
            s00 = __ldg(r00 + off);
            s01 = __ldg(r01 + off);
            s10 = __ldg(r10 + off);
            s11 = __ldg(r11 + off);
        }

        // Select the two x-corners from each float4 (SEL chains, no spill).
        #define SEL_V0(q) ((r == 0) ? (q).x : (r == 1) ? (q).y : (r == 2) ? (q).z : (q).w)
        #define SEL_V1(q, s) ((r == 0) ? (q).y : (r == 1) ? (q).z : (r == 2) ? (q).w : (s))
        float v000 = SEL_V0(q00), v001 = SEL_V1(q00, s00);
        float v010 = SEL_V0(q01), v011 = SEL_V1(q01, s01);
        float v100 = SEL_V0(q10), v101 = SEL_V1(q10, s10);
        float v110 = SEL_V0(q11), v111 = SEL_V1(q11, s11);
        #undef SEL_V0
        #undef SEL_V1

        float c00 = v000 + tx * (v001 - v000);
        float c01 = v010 + tx * (v011 - v010);
        float c10 = v100 + tx * (v101 - v100);
        float c11 = v110 + tx * (v111 - v110);
        float c0  = c00 + ty * (c01 - c00);
        float c1  = c10 + ty * (c11 - c10);
        result = c0 + tz * (c1 - c0);
    } else {
        int x1 = x0 + 1, y1 = y0 + 1, z1 = z0 + 1;
        float v000 = gather(vol, z0, y0, x0);
        float v001 = gather(vol, z0, y0, x1);
        float v010 = gather(vol, z0, y1, x0);
        float v011 = gather(vol, z0, y1, x1);
        float v100 = gather(vol, z1, y0, x0);
        float v101 = gather(vol, z1, y0, x1);
        float v110 = gather(vol, z1, y1, x0);
        float v111 = gather(vol, z1, y1, x1);
        float c00 = v000 + tx * (v001 - v000);
        float c01 = v010 + tx * (v011 - v010);
        float c10 = v100 + tx * (v101 - v100);
        float c11 = v110 + tx * (v111 - v110);
        float c0  = c00 + ty * (c01 - c00);
        float c1  = c10 + ty * (c11 - c10);
        result = c0 + tz * (c1 - c0);
    }

    out[i] = result;
}

extern "C" void kernel_launch(void* const* d_in, const int* in_sizes, int n_in,
                              void* d_out, int out_size) {
    const float4* xyz  = (const float4*)d_in[0];
    const float*  vol  = (const float*)d_in[1];
    const float*  aabb = (const float*)d_in[2];
    const int*    cs   = (const int*)d_in[3];
    float* out = (float*)d_out;

    int n = out_size;
    int threads = 256;
    int blocks = (n + threads - 1) / threads;
    alpha_grid_mask_kernel<<<blocks, threads>>>(xyz, vol, aabb, cs, out, n);
}

// round 3
// speedup vs baseline: 1.1696x; 1.1169x over previous
#include <cuda_runtime.h>
#include <cuda_fp16.h>
#include <cstdint>

#define DHW 256

// Blocked fp16 volume: 2x2x2 voxel blocks of 8 halfs (16B).
// idx = z[7:1] y[7:1] x[7:1] | z[0] y[0] x[0]
__device__ __half g_blk[1 << 24];   // 16.7M halfs = 33.5 MB

__device__ __forceinline__ int blk_idx(int x, int y, int z) {
    return ((z >> 1) << 17) | ((y >> 1) << 10) | ((x >> 1) << 3)
         | ((z & 1) << 2) | ((y & 1) << 1) | (x & 1);
}

// One thread per 2x2x2 block: 4 coalesced float2 reads, one 16B write.
__global__ void __launch_bounds__(256)
convert_kernel(const float* __restrict__ vol) {
    int b = blockIdx.x * blockDim.x + threadIdx.x;   // 2^21 blocks
    int bx = b & 127, by = (b >> 7) & 127, bz = b >> 14;
    const float* p = vol + ((bz << 17) | (by << 9) | (bx << 1));
    float2 r000 = *(const float2*)(p);
    float2 r010 = *(const float2*)(p + 256);
    float2 r100 = *(const float2*)(p + 65536);
    float2 r110 = *(const float2*)(p + 65536 + 256);
    __half2 h0 = __floats2half2_rn(r000.x, r000.y);
    __half2 h1 = __floats2half2_rn(r010.x, r010.y);
    __half2 h2 = __floats2half2_rn(r100.x, r100.y);
    __half2 h3 = __floats2half2_rn(r110.x, r110.y);
    uint4 o;
    o.x = *(unsigned*)&h0;  o.y = *(unsigned*)&h1;
    o.z = *(unsigned*)&h2;  o.w = *(unsigned*)&h3;
    ((uint4*)g_blk)[b] = o;
}

// Fallback path (contract_space == 0): exact fp32 gather with zero padding.
__device__ __forceinline__ float gather(const float* __restrict__ vol,
                                        int z, int y, int x) {
    if ((unsigned)z < (unsigned)DHW &&
        (unsigned)y < (unsigned)DHW &&
        (unsigned)x < (unsigned)DHW) {
        return __ldg(vol + ((z << 16) | (y << 8) | x));
    }
    return 0.0f;
}

struct Coord {
    int x0, y0, z0, x1, y1, z1;
    float tx, ty, tz;
    bool valid;
};

__device__ __forceinline__ Coord make_coord(float4 p,
                                            float a0x, float a0y, float a0z,
                                            float igx, float igy, float igz,
                                            int cs) {
    float cx = (p.x - a0x) * igx - 1.0f;
    float cy = (p.y - a0y) * igy - 1.0f;
    float cz = (p.z - a0z) * igz - 1.0f;
    if (cs != 0) {
        float dist = fmaxf(fabsf(cx), fmaxf(fabsf(cy), fabsf(cz))) + 1e-8f;
        float scale = (dist > 1.0f) ? (2.0f - 1.0f / dist) : dist;
        float m = scale * 0.5f / dist;
        cx *= m; cy *= m; cz *= m;
    }
    const float half_span = 0.5f * (DHW - 1);
    float ix = (cx + 1.0f) * half_span;
    float iy = (cy + 1.0f) * half_span;
    float iz = (cz + 1.0f) * half_span;
    float x0f = floorf(ix), y0f = floorf(iy), z0f = floorf(iz);
    Coord c;
    c.tx = ix - x0f; c.ty = iy - y0f; c.tz = iz - z0f;
    int x0 = (int)x0f, y0 = (int)y0f, z0 = (int)z0f;
    // Contracted coords are strictly inside (-1,1): clamps only catch
    // float-rounding at the boundary, where the dropped weight is 0.
    c.x0 = min(max(x0, 0), DHW - 1);
    c.y0 = min(max(y0, 0), DHW - 1);
    c.z0 = min(max(z0, 0), DHW - 1);
    c.x1 = min(c.x0 + 1, DHW - 1);
    c.y1 = min(c.y0 + 1, DHW - 1);
    c.z1 = min(c.z0 + 1, DHW - 1);
    c.valid = true;
    return c;
}

__device__ __forceinline__ float lerp3(float v000, float v001, float v010, float v011,
                                       float v100, float v101, float v110, float v111,
                                       float tx, float ty, float tz) {
    float c00 = v000 + tx * (v001 - v000);
    float c01 = v010 + tx * (v011 - v010);
    float c10 = v100 + tx * (v101 - v100);
    float c11 = v110 + tx * (v111 - v110);
    float c0  = c00 + ty * (c01 - c00);
    float c1  = c10 + ty * (c11 - c10);
    return c0 + tz * (c1 - c0);
}

__global__ void __launch_bounds__(256)
sample_kernel(const float4* __restrict__ xyz,
              const float* __restrict__ vol,
              const float* __restrict__ aabb,
              const int*   __restrict__ cspace,
              float* __restrict__ out,
              int n) {
    int base = (blockIdx.x * blockDim.x + threadIdx.x) * 2;
    if (base >= n) return;

    float a0x = __ldg(aabb + 0), a0y = __ldg(aabb + 1), a0z = __ldg(aabb + 2);
    float a1x = __ldg(aabb + 3), a1y = __ldg(aabb + 4), a1z = __ldg(aabb + 5);
    float igx = 2.0f / (a1x - a0x);
    float igy = 2.0f / (a1y - a0y);
    float igz = 2.0f / (a1z - a0z);
    int cs = __ldg(cspace);

    bool has1 = (base + 1) < n;
    float4 pA = __ldg(xyz + base);
    float4 pB = has1 ? __ldg(xyz + base + 1) : pA;

    Coord A = make_coord(pA, a0x, a0y, a0z, igx, igy, igz, cs);
    Coord B = make_coord(pB, a0x, a0y, a0z, igx, igy, igz, cs);

    if (cs != 0) {
        const __half* blk = g_blk;
        // 16 gathers issued back-to-back: MLP=16 hides L2 latency.
        float a000 = __half2float(__ldg(blk + blk_idx(A.x0, A.y0, A.z0)));
        float a001 = __half2float(__ldg(blk + blk_idx(A.x1, A.y0, A.z0)));
        float a010 = __half2float(__ldg(blk + blk_idx(A.x0, A.y1, A.z0)));
        float a011 = __half2float(__ldg(blk + blk_idx(A.x1, A.y1, A.z0)));
        float a100 = __half2float(__ldg(blk + blk_idx(A.x0, A.y0, A.z1)));
        float a101 = __half2float(__ldg(blk + blk_idx(A.x1, A.y0, A.z1)));
        float a110 = __half2float(__ldg(blk + blk_idx(A.x0, A.y1, A.z1)));
        float a111 = __half2float(__ldg(blk + blk_idx(A.x1, A.y1, A.z1)));
        float b000 = __half2float(__ldg(blk + blk_idx(B.x0, B.y0, B.z0)));
        float b001 = __half2float(__ldg(blk + blk_idx(B.x1, B.y0, B.z0)));
        float b010 = __half2float(__ldg(blk + blk_idx(B.x0, B.y1, B.z0)));
        float b011 = __half2float(__ldg(blk + blk_idx(B.x1, B.y1, B.z0)));
        float b100 = __half2float(__ldg(blk + blk_idx(B.x0, B.y0, B.z1)));
        float b101 = __half2float(__ldg(blk + blk_idx(B.x1, B.y0, B.z1)));
        float b110 = __half2float(__ldg(blk + blk_idx(B.x0, B.y1, B.z1)));
        float b111 = __half2float(__ldg(blk + blk_idx(B.x1, B.y1, B.z1)));

        out[base] = lerp3(a000, a001, a010, a011, a100, a101, a110, a111,
                          A.tx, A.ty, A.tz);
        if (has1)
            out[base + 1] = lerp3(b000, b001, b010, b011, b100, b101, b110, b111,
                                  B.tx, B.ty, B.tz);
    } else {
        // Exact fp32 path with zero padding (unclamped indices recomputed).
        #pragma unroll
        for (int k = 0; k < 2; k++) {
            int i = base + k;
            if (i >= n) break;
            float4 p = (k == 0) ? pA : pB;
            float cx = (p.x - a0x) * igx - 1.0f;
            float cy = (p.y - a0y) * igy - 1.0f;
            float cz = (p.z - a0z) * igz - 1.0f;
            const float half_span = 0.5f * (DHW - 1);
            float ix = (cx + 1.0f) * half_span;
            float iy = (cy + 1.0f) * half_span;
            float iz = (cz + 1.0f) * half_span;
            float x0f = floorf(ix), y0f = floorf(iy), z0f = floorf(iz);
            float tx = ix - x0f, ty = iy - y0f, tz = iz - z0f;
            int x0 = (int)x0f, y0 = (int)y0f, z0 = (int)z0f;
            float v000 = gather(vol, z0, y0, x0);
            float v001 = gather(vol, z0, y0, x0 + 1);
            float v010 = gather(vol, z0, y0 + 1, x0);
            float v011 = gather(vol, z0, y0 + 1, x0 + 1);
            float v100 = gather(vol, z0 + 1, y0, x0);
            float v101 = gather(vol, z0 + 1, y0, x0 + 1);
            float v110 = gather(vol, z0 + 1, y0 + 1, x0);
            float v111 = gather(vol, z0 + 1, y0 + 1, x0 + 1);
            out[i] = lerp3(v000, v001, v010, v011, v100, v101, v110, v111,
                           tx, ty, tz);
        }
    }
}

extern "C" void kernel_launch(void* const* d_in, const int* in_sizes, int n_in,
                              void* d_out, int out_size) {
    const float4* xyz  = (const float4*)d_in[0];
    const float*  vol  = (const float*)d_in[1];
    const float*  aabb = (const float*)d_in[2];
    const int*    cs   = (const int*)d_in[3];
    float* out = (float*)d_out;
    int n = out_size;

    // Pass 1: re-layout volume into blocked fp16 (2^21 blocks).
    convert_kernel<<<(1 << 21) / 256, 256>>>(vol);

    // Pass 2: sample, 2 points per thread.
    int threads = 256;
    int pts_per_blk = threads * 2;
    int blocks = (n + pts_per_blk - 1) / pts_per_blk;
    sample_kernel<<<blocks, threads>>>(xyz, vol, aabb, cs, out, n);
}

// round 4
// speedup vs baseline: 1.2909x; 1.1037x over previous
#include <cuda_runtime.h>
#include <cuda_fp16.h>
#include <cstdint>

#define DHW 256

// Pair table: P[z][y][x] = (v[z][y][x], v[z][y][min(x+1,255)]) as half2.
// Layout (half2 units): idx = z[7:1] y[7:1] x[7:2] z[0] y[0] x[1:0]
// -> one 32B sector holds 4 x-groups x (y0,y1) x (z0,z1): the 4 gathers of a
//    trilinear sample hit ~2.25 distinct sectors on average.
__device__ __half2 g_pair[1 << 24];   // 67 MB

__device__ __forceinline__ int pidx(int x, int y, int z) {
    return ((z >> 1) << 17) | ((y >> 1) << 10) | ((x >> 2) << 4)
         | ((z & 1) << 3) | ((y & 1) << 2) | (x & 3);
}

// Build the pair table. Thread t covers (z, y0..y0+1, x-group of 4):
// bits of t: [z'(7)][y'(7)][z0(1)][xg(6)] so a warp reads rows coalesced.
__global__ void __launch_bounds__(256)
convert_kernel(const float* __restrict__ vol) {
    int t = blockIdx.x * blockDim.x + threadIdx.x;   // 2^21 threads
    int xg = t & 63;
    int z0 = (t >> 6) & 1;
    int yp = (t >> 7) & 127;
    int zp = t >> 14;
    int z = (zp << 1) | z0;
    int y = yp << 1;

    const float* r0 = vol + ((z << 16) | (y << 8) | (xg << 2));
    const float* r1 = r0 + 256;
    float4 a = *(const float4*)r0;
    float4 b = *(const float4*)r1;
    float a4 = (xg == 63) ? a.w : __ldg(r0 + 4);
    float b4 = (xg == 63) ? b.w : __ldg(r1 + 4);

    __half2 h0 = __floats2half2_rn(a.x, a.y);
    __half2 h1 = __floats2half2_rn(a.y, a.z);
    __half2 h2 = __floats2half2_rn(a.z, a.w);
    __half2 h3 = __floats2half2_rn(a.w, a4);
    __half2 h4 = __floats2half2_rn(b.x, b.y);
    __half2 h5 = __floats2half2_rn(b.y, b.z);
    __half2 h6 = __floats2half2_rn(b.z, b.w);
    __half2 h7 = __floats2half2_rn(b.w, b4);

    // base half2 index (z0 parity bit set, y parity = 0, x bits = 0): 16B aligned
    int base = (zp << 17) | (yp << 10) | (xg << 4) | (z0 << 3);
    uint4* o = (uint4*)(g_pair + base);
    uint4 w0, w1;
    w0.x = *(unsigned*)&h0; w0.y = *(unsigned*)&h1;
    w0.z = *(unsigned*)&h2; w0.w = *(unsigned*)&h3;
    w1.x = *(unsigned*)&h4; w1.y = *(unsigned*)&h5;
    w1.z = *(unsigned*)&h6; w1.w = *(unsigned*)&h7;
    o[0] = w0;   // y even (offsets +0..3)
    o[1] = w1;   // y odd  (offsets +4..7)
}

// Exact fp32 gather for the contract_space == 0 fallback.
__device__ __forceinline__ float gather(const float* __restrict__ vol,
                                        int z, int y, int x) {
    if ((unsigned)z < (unsigned)DHW &&
        (unsigned)y < (unsigned)DHW &&
        (unsigned)x < (unsigned)DHW) {
        return __ldg(vol + ((z << 16) | (y << 8) | x));
    }
    return 0.0f;
}

struct Coord {
    int x0, y0, z0, y1, z1;
    float tx, ty, tz;
};

__device__ __forceinline__ Coord make_coord(float4 p,
                                            float a0x, float a0y, float a0z,
                                            float igx, float igy, float igz) {
    float cx = (p.x - a0x) * igx - 1.0f;
    float cy = (p.y - a0y) * igy - 1.0f;
    float cz = (p.z - a0z) * igz - 1.0f;
    float dist = fmaxf(fabsf(cx), fmaxf(fabsf(cy), fabsf(cz))) + 1e-8f;
    float scale = (dist > 1.0f) ? (2.0f - 1.0f / dist) : dist;
    float m = scale * 0.5f / dist;
    cx *= m; cy *= m; cz *= m;

    const float half_span = 0.5f * (DHW - 1);
    float ix = (cx + 1.0f) * half_span;
    float iy = (cy + 1.0f) * half_span;
    float iz = (cz + 1.0f) * half_span;
    float x0f = floorf(ix), y0f = floorf(iy), z0f = floorf(iz);
    Coord c;
    c.tx = ix - x0f; c.ty = iy - y0f; c.tz = iz - z0f;
    // Contracted coords are strictly inside (-1,1); clamps only catch
    // float-rounding at the boundary (dropped lerp weight is exactly 0, and
    // the pair table stores (v255, v255) at x=255).
    c.x0 = min(max((int)x0f, 0), DHW - 1);
    c.y0 = min(max((int)y0f, 0), DHW - 1);
    c.z0 = min(max((int)z0f, 0), DHW - 1);
    c.y1 = min(c.y0 + 1, DHW - 1);
    c.z1 = min(c.z0 + 1, DHW - 1);
    return c;
}

__device__ __forceinline__ float lerp_pairs(float2 v00, float2 v01,
                                            float2 v10, float2 v11,
                                            float tx, float ty, float tz) {
    float c00 = v00.x + tx * (v00.y - v00.x);
    float c01 = v01.x + tx * (v01.y - v01.x);
    float c10 = v10.x + tx * (v10.y - v10.x);
    float c11 = v11.x + tx * (v11.y - v11.x);
    float c0  = c00 + ty * (c01 - c00);
    float c1  = c10 + ty * (c11 - c10);
    return c0 + tz * (c1 - c0);
}

__global__ void __launch_bounds__(256)
sample_kernel(const float4* __restrict__ xyz,
              const float* __restrict__ vol,
              const float* __restrict__ aabb,
              const int*   __restrict__ cspace,
              float* __restrict__ out,
              int n) {
    int base = (blockIdx.x * blockDim.x + threadIdx.x) * 2;
    if (base >= n) return;

    float a0x = __ldg(aabb + 0), a0y = __ldg(aabb + 1), a0z = __ldg(aabb + 2);
    float a1x = __ldg(aabb + 3), a1y = __ldg(aabb + 4), a1z = __ldg(aabb + 5);
    float igx = 2.0f / (a1x - a0x);
    float igy = 2.0f / (a1y - a0y);
    float igz = 2.0f / (a1z - a0z);
    int cs = __ldg(cspace);

    bool has1 = (base + 1) < n;
    float4 pA = __ldg(xyz + base);
    float4 pB = has1 ? __ldg(xyz + base + 1) : pA;

    if (cs != 0) {
        Coord A = make_coord(pA, a0x, a0y, a0z, igx, igy, igz);
        Coord B = make_coord(pB, a0x, a0y, a0z, igx, igy, igz);

        const __half2* P = g_pair;
        // 8 gathers issued back-to-back (MLP=8): one half2 per (y,z) corner,
        // containing both x-corners.
        __half2 hA00 = __ldg(P + pidx(A.x0, A.y0, A.z0));
        __half2 hA01 = __ldg(P + pidx(A.x0, A.y1, A.z0));
        __half2 hA10 = __ldg(P + pidx(A.x0, A.y0, A.z1));
        __half2 hA11 = __ldg(P + pidx(A.x0, A.y1, A.z1));
        __half2 hB00 = __ldg(P + pidx(B.x0, B.y0, B.z0));
        __half2 hB01 = __ldg(P + pidx(B.x0, B.y1, B.z0));
        __half2 hB10 = __ldg(P + pidx(B.x0, B.y0, B.z1));
        __half2 hB11 = __ldg(P + pidx(B.x0, B.y1, B.z1));

        out[base] = lerp_pairs(__half22float2(hA00), __half22float2(hA01),
                               __half22float2(hA10), __half22float2(hA11),
                               A.tx, A.ty, A.tz);
        if (has1)
            out[base + 1] = lerp_pairs(__half22float2(hB00), __half22float2(hB01),
                                       __half22float2(hB10), __half22float2(hB11),
                                       B.tx, B.ty, B.tz);
    } else {
        // Exact fp32 path with zero padding.
        #pragma unroll
        for (int k = 0; k < 2; k++) {
            int i = base + k;
            if (i >= n) break;
            float4 p = (k == 0) ? pA : pB;
            float cx = (p.x - a0x) * igx - 1.0f;
            float cy = (p.y - a0y) * igy - 1.0f;
            float cz = (p.z - a0z) * igz - 1.0f;
            const float half_span = 0.5f * (DHW - 1);
            float ix = (cx + 1.0f) * half_span;
            float iy = (cy + 1.0f) * half_span;
            float iz = (cz + 1.0f) * half_span;
            float x0f = floorf(ix), y0f = floorf(iy), z0f = floorf(iz);
            float tx = ix - x0f, ty = iy - y0f, tz = iz - z0f;
            int x0 = (int)x0f, y0 = (int)y0f, z0 = (int)z0f;
            float v000 = gather(vol, z0, y0, x0);
            float v001 = gather(vol, z0, y0, x0 + 1);
            float v010 = gather(vol, z0, y0 + 1, x0);
            float v011 = gather(vol, z0, y0 + 1, x0 + 1);
            float v100 = gather(vol, z0 + 1, y0, x0);
            float v101 = gather(vol, z0 + 1, y0, x0 + 1);
            float v110 = gather(vol, z0 + 1, y0 + 1, x0);
            float v111 = gather(vol, z0 + 1, y0 + 1, x0 + 1);
            float c00 = v000 + tx * (v001 - v000);
            float c01 = v010 + tx * (v011 - v010);
            float c10 = v100 + tx * (v101 - v100);
            float c11 = v110 + tx * (v111 - v110);
            float c0  = c00 + ty * (c01 - c00);
            float c1  = c10 + ty * (c11 - c10);
            out[i] = c0 + tz * (c1 - c0);
        }
    }
}

extern "C" void kernel_launch(void* const* d_in, const int* in_sizes, int n_in,
                              void* d_out, int out_size) {
    const float4* xyz  = (const float4*)d_in[0];
    const float*  vol  = (const float*)d_in[1];
    const float*  aabb = (const float*)d_in[2];
    const int*    cs   = (const int*)d_in[3];
    float* out = (float*)d_out;
    int n = out_size;

    convert_kernel<<<(1 << 21) / 256, 256>>>(vol);

    int threads = 256;
    int pts_per_blk = threads * 2;
    int blocks = (n + pts_per_blk - 1) / pts_per_blk;
    sample_kernel<<<blocks, threads>>>(xyz, vol, aabb, cs, out, n);
}

// round 5
// speedup vs baseline: 1.5249x; 1.1813x over previous
#include <cuda_runtime.h>
#include <cuda_fp16.h>
#include <cstdint>

#define DHW 256

// Quad table: Q[z][y][x] = {v[z][y][x], v[z][y][x+1c], v[z][y+1c][x], v[z][y+1c][x+1c]}
// as 4 fp16 (8 B). Layout in 8B units:
//   idx = z[7:1] y[7:0] x[7:0] z[0]
// so the (z=2k, z=2k+1) entries of the same (x,y) are one aligned 16B uint4:
// a single 16B load returns all 8 trilinear corners when z0 is even.
__device__ uint2 g_quad[1 << 24];   // 134 MB

// Convert: thread t covers x-group of 4, one y, one z-pair (z=2k, 2k+1).
// Writes 8 entries = 64B contiguous; fully coalesced across consecutive threads.
__global__ void __launch_bounds__(256)
convert_kernel(const float* __restrict__ vol) {
    int t  = blockIdx.x * blockDim.x + threadIdx.x;   // 2^21 threads
    int xg = t & 63;
    int y  = (t >> 6) & 255;
    int k  = t >> 14;                                  // z-pair index 0..127
    int x  = xg << 2;
    int z  = k << 1;

    const float* r00 = vol + ((z << 16) | (y << 8) | x);          // (z,   y  )
    const float* r01 = (y < 255) ? r00 + 256   : r00;             // (z,   y+1c)
    const float* r10 = r00 + 65536;                               // (z+1, y  )
    const float* r11 = (y < 255) ? r10 + 256   : r10;             // (z+1, y+1c)

    float4 a0 = *(const float4*)r00;
    float4 a1 = *(const float4*)r01;
    float4 b0 = *(const float4*)r10;
    float4 b1 = *(const float4*)r11;
    bool edge = (xg == 63);
    float a0e = edge ? a0.w : __ldg(r00 + 4);
    float a1e = edge ? a1.w : __ldg(r01 + 4);
    float b0e = edge ? b0.w : __ldg(r10 + 4);
    float b1e = edge ? b1.w : __ldg(r11 + 4);

    float A0[5] = {a0.x, a0.y, a0.z, a0.w, a0e};
    float A1[5] = {a1.x, a1.y, a1.z, a1.w, a1e};
    float B0[5] = {b0.x, b0.y, b0.z, b0.w, b0e};
    float B1[5] = {b1.x, b1.y, b1.z, b1.w, b1e};

    uint4* dst = (uint4*)g_quad + ((unsigned)t << 2);
    #pragma unroll
    for (int j = 0; j < 4; j++) {
        __half2 e0 = __floats2half2_rn(A0[j], A0[j + 1]);  // z even, y row
        __half2 e1 = __floats2half2_rn(A1[j], A1[j + 1]);  // z even, y+1 row
        __half2 f0 = __floats2half2_rn(B0[j], B0[j + 1]);  // z odd,  y row
        __half2 f1 = __floats2half2_rn(B1[j], B1[j + 1]);  // z odd,  y+1 row
        uint4 w;
        w.x = *(unsigned*)&e0; w.y = *(unsigned*)&e1;
        w.z = *(unsigned*)&f0; w.w = *(unsigned*)&f1;
        dst[j] = w;
    }
}

// Exact fp32 gather for the contract_space == 0 fallback.
__device__ __forceinline__ float gather(const float* __restrict__ vol,
                                        int z, int y, int x) {
    if ((unsigned)z < (unsigned)DHW &&
        (unsigned)y < (unsigned)DHW &&
        (unsigned)x < (unsigned)DHW) {
        return __ldg(vol + ((z << 16) | (y << 8) | x));
    }
    return 0.0f;
}

struct Coord {
    int x0, y0, z0;
    float tx, ty, tz;
};

__device__ __forceinline__ Coord make_coord(float4 p,
                                            float a0x, float a0y, float a0z,
                                            float igx, float igy, float igz) {
    float cx = (p.x - a0x) * igx - 1.0f;
    float cy = (p.y - a0y) * igy - 1.0f;
    float cz = (p.z - a0z) * igz - 1.0f;
    float dist = fmaxf(fabsf(cx), fmaxf(fabsf(cy), fabsf(cz))) + 1e-8f;
    float scale = (dist > 1.0f) ? (2.0f - 1.0f / dist) : dist;
    float m = scale * 0.5f / dist;
    cx *= m; cy *= m; cz *= m;

    const float half_span = 0.5f * (DHW - 1);
    float ix = (cx + 1.0f) * half_span;
    float iy = (cy + 1.0f) * half_span;
    float iz = (cz + 1.0f) * half_span;
    float x0f = floorf(ix), y0f = floorf(iy), z0f = floorf(iz);
    Coord c;
    c.tx = ix - x0f; c.ty = iy - y0f; c.tz = iz - z0f;
    // Contraction bounds |coord| <= ~0.63, so indices are interior; clamps are
    // pure rounding safety (dropped lerp weight is exactly 0 at a boundary).
    c.x0 = min(max((int)x0f, 0), DHW - 2);
    c.y0 = min(max((int)y0f, 0), DHW - 2);
    c.z0 = min(max((int)z0f, 0), DHW - 2);
    return c;
}

// Full trilerp from two quads (lo = layer z0, hi = layer z1), each packed as
// two half2: {v[x],v[x+1]}@y , {v[x],v[x+1]}@y+1.
__device__ __forceinline__ float lerp_quads(uint2 lo, uint2 hi,
                                            float tx, float ty, float tz) {
    float2 l0 = __half22float2(*(__half2*)&lo.x);
    float2 l1 = __half22float2(*(__half2*)&lo.y);
    float2 h0 = __half22float2(*(__half2*)&hi.x);
    float2 h1 = __half22float2(*(__half2*)&hi.y);
    float c00 = l0.x + tx * (l0.y - l0.x);
    float c01 = l1.x + tx * (l1.y - l1.x);
    float c10 = h0.x + tx * (h0.y - h0.x);
    float c11 = h1.x + tx * (h1.y - h1.x);
    float c0  = c00 + ty * (c01 - c00);
    float c1  = c10 + ty * (c11 - c10);
    return c0 + tz * (c1 - c0);
}

__device__ __forceinline__ float sample_point(Coord c) {
    int k  = c.z0 >> 1;
    int zp = c.z0 & 1;
    // Aligned 16B unit holding (z=2k, z=2k+1) quads of (x0, y0).
    const uint4* p16 = (const uint4*)g_quad + ((k << 16) | (c.y0 << 8) | c.x0);
    uint4 Q = __ldg(p16);
    uint2 F = make_uint2(0u, 0u);
    if (zp) {
        // z1 = z0+1 = 2(k+1): low half of the next z-pair.
        F = __ldg(g_quad + ((((k + 1) << 17) | (c.y0 << 9) | (c.x0 << 1))));
    }
    uint2 lo = zp ? make_uint2(Q.z, Q.w) : make_uint2(Q.x, Q.y);
    uint2 hi = zp ? F                    : make_uint2(Q.z, Q.w);
    return lerp_quads(lo, hi, c.tx, c.ty, c.tz);
}

__global__ void __launch_bounds__(256)
sample_kernel(const float4* __restrict__ xyz,
              const float* __restrict__ vol,
              const float* __restrict__ aabb,
              const int*   __restrict__ cspace,
              float* __restrict__ out,
              int n) {
    int base = (blockIdx.x * blockDim.x + threadIdx.x) * 2;
    if (base >= n) return;

    float a0x = __ldg(aabb + 0), a0y = __ldg(aabb + 1), a0z = __ldg(aabb + 2);
    float a1x = __ldg(aabb + 3), a1y = __ldg(aabb + 4), a1z = __ldg(aabb + 5);
    float igx = 2.0f / (a1x - a0x);
    float igy = 2.0f / (a1y - a0y);
    float igz = 2.0f / (a1z - a0z);
    int cs = __ldg(cspace);

    bool has1 = (base + 1) < n;
    float4 pA = __ldg(xyz + base);
    float4 pB = has1 ? __ldg(xyz + base + 1) : pA;

    if (cs != 0) {
        Coord A = make_coord(pA, a0x, a0y, a0z, igx, igy, igz);
        Coord B = make_coord(pB, a0x, a0y, a0z, igx, igy, igz);
        float rA = sample_point(A);
        float rB = sample_point(B);
        out[base] = rA;
        if (has1) out[base + 1] = rB;
    } else {
        // Exact fp32 path with zero padding.
        #pragma unroll
        for (int kk = 0; kk < 2; kk++) {
            int i = base + kk;
            if (i >= n) break;
            float4 p = (kk == 0) ? pA : pB;
            float cx = (p.x - a0x) * igx - 1.0f;
            float cy = (p.y - a0y) * igy - 1.0f;
            float cz = (p.z - a0z) * igz - 1.0f;
            const float half_span = 0.5f * (DHW - 1);
            float ix = (cx + 1.0f) * half_span;
            float iy = (cy + 1.0f) * half_span;
            float iz = (cz + 1.0f) * half_span;
            float x0f = floorf(ix), y0f = floorf(iy), z0f = floorf(iz);
            float tx = ix - x0f, ty = iy - y0f, tz = iz - z0f;
            int x0 = (int)x0f, y0 = (int)y0f, z0 = (int)z0f;
            float v000 = gather(vol, z0, y0, x0);
            float v001 = gather(vol, z0, y0, x0 + 1);
            float v010 = gather(vol, z0, y0 + 1, x0);
            float v011 = gather(vol, z0, y0 + 1, x0 + 1);
            float v100 = gather(vol, z0 + 1, y0, x0);
            float v101 = gather(vol, z0 + 1, y0, x0 + 1);
            float v110 = gather(vol, z0 + 1, y0 + 1, x0);
            float v111 = gather(vol, z0 + 1, y0 + 1, x0 + 1);
            float c00 = v000 + tx * (v001 - v000);
            float c01 = v010 + tx * (v011 - v010);
            float c10 = v100 + tx * (v101 - v100);
            float c11 = v110 + tx * (v111 - v110);
            float c0  = c00 + ty * (c01 - c00);
            float c1  = c10 + ty * (c11 - c10);
            out[i] = c0 + tz * (c1 - c0);
        }
    }
}

extern "C" void kernel_launch(void* const* d_in, const int* in_sizes, int n_in,
                              void* d_out, int out_size) {
    const float4* xyz  = (const float4*)d_in[0];
    const float*  vol  = (const float*)d_in[1];
    const float*  aabb = (const float*)d_in[2];
    const int*    cs   = (const int*)d_in[3];
    float* out = (float*)d_out;
    int n = out_size;

    convert_kernel<<<(1 << 21) / 256, 256>>>(vol);

    int threads = 256;
    int pts_per_blk = threads * 2;
    int blocks = (n + pts_per_blk - 1) / pts_per_blk;
    sample_kernel<<<blocks, threads>>>(xyz, vol, aabb, cs, out, n);
}

// round 6
// speedup vs baseline: 2.0432x; 1.3399x over previous
#include <cuda_runtime.h>
#include <cuda_fp16.h>
#include <cstdint>

#define DHW 256

// Windowed quad table. Contracted coords for this problem satisfy
// |coord| <= 0.625 -> grid indices in [47.8, 207.2]; window [44, 211] with
// margin. Any index outside the window takes the exact fp32 fallback path.
#define WLO 44
#define WS  168            // window span (even)
#define WK  (WS / 2)       // z-pairs
#define WMAXI (WS - 2)     // max in-window local index (need +1 neighbor)

// Entry (k, yi, xi) packs the 8 trilinear corners of base (x,y,z=2k+WLO):
//  .x = (v[z][y][x],   v[z][y][x+1])     .y = (v[z][y+1][x],   v[z][y+1][x+1])
//  .z = (v[z+1][y][x], v[z+1][y][x+1])   .w = (v[z+1][y+1][x], v[z+1][y+1][x+1])
// all fp16. 84*168*168*16B = 37.9 MB -> fully L2-resident.
__device__ uint4 g_quad[WK * WS * WS];

#define CONV_XG (WS / 4)                       // 42 x-groups of 4
#define CONV_TOTAL (WK * WS * CONV_XG)         // 592,704 threads

__global__ void __launch_bounds__(256)
convert_kernel(const float* __restrict__ vol) {
    int t = blockIdx.x * blockDim.x + threadIdx.x;
    if (t >= CONV_TOTAL) return;
    int xg   = t % CONV_XG;
    int rest = t / CONV_XG;
    int yi   = rest % WS;
    int k    = rest / WS;

    int x = WLO + (xg << 2);     // divisible by 4 -> aligned float4 reads
    int y = WLO + yi;
    int z = WLO + (k << 1);

    // Window+1 stays < 256 everywhere: no edge clamps needed.
    const float* r00 = vol + ((z << 16) | (y << 8) | x);
    const float* r01 = r00 + 256;       // y+1
    const float* r10 = r00 + 65536;     // z+1
    const float* r11 = r10 + 256;       // z+1, y+1

    float4 a0 = *(const float4*)r00;  float a0e = __ldg(r00 + 4);
    float4 a1 = *(const float4*)r01;  float a1e = __ldg(r01 + 4);
    float4 b0 = *(const float4*)r10;  float b0e = __ldg(r10 + 4);
    float4 b1 = *(const float4*)r11;  float b1e = __ldg(r11 + 4);

    float A0[5] = {a0.x, a0.y, a0.z, a0.w, a0e};
    float A1[5] = {a1.x, a1.y, a1.z, a1.w, a1e};
    float B0[5] = {b0.x, b0.y, b0.z, b0.w, b0e};
    float B1[5] = {b1.x, b1.y, b1.z, b1.w, b1e};

    uint4* dst = g_quad + ((k * WS + yi) * WS + (xg << 2));
    #pragma unroll
    for (int j = 0; j < 4; j++) {
        __half2 e0 = __floats2half2_rn(A0[j], A0[j + 1]);
        __half2 e1 = __floats2half2_rn(A1[j], A1[j + 1]);
        __half2 f0 = __floats2half2_rn(B0[j], B0[j + 1]);
        __half2 f1 = __floats2half2_rn(B1[j], B1[j + 1]);
        uint4 w;
        w.x = *(unsigned*)&e0; w.y = *(unsigned*)&e1;
        w.z = *(unsigned*)&f0; w.w = *(unsigned*)&f1;
        dst[j] = w;
    }
}

// Exact fp32 gather with zero padding (fallback + cs==0 path).
__device__ __forceinline__ float gather(const float* __restrict__ vol,
                                        int z, int y, int x) {
    if ((unsigned)z < (unsigned)DHW &&
        (unsigned)y < (unsigned)DHW &&
        (unsigned)x < (unsigned)DHW) {
        return __ldg(vol + ((z << 16) | (y << 8) | x));
    }
    return 0.0f;
}

__device__ __forceinline__ float sample_fp32(const float* __restrict__ vol,
                                             float ix, float iy, float iz) {
    float x0f = floorf(ix), y0f = floorf(iy), z0f = floorf(iz);
    float tx = ix - x0f, ty = iy - y0f, tz = iz - z0f;
    int x0 = (int)x0f, y0 = (int)y0f, z0 = (int)z0f;
    float v000 = gather(vol, z0, y0, x0);
    float v001 = gather(vol, z0, y0, x0 + 1);
    float v010 = gather(vol, z0, y0 + 1, x0);
    float v011 = gather(vol, z0, y0 + 1, x0 + 1);
    float v100 = gather(vol, z0 + 1, y0, x0);
    float v101 = gather(vol, z0 + 1, y0, x0 + 1);
    float v110 = gather(vol, z0 + 1, y0 + 1, x0);
    float v111 = gather(vol, z0 + 1, y0 + 1, x0 + 1);
    float c00 = v000 + tx * (v001 - v000);
    float c01 = v010 + tx * (v011 - v010);
    float c10 = v100 + tx * (v101 - v100);
    float c11 = v110 + tx * (v111 - v110);
    float c0  = c00 + ty * (c01 - c00);
    float c1  = c10 + ty * (c11 - c10);
    return c0 + tz * (c1 - c0);
}

__device__ __forceinline__ float lerp_quads(uint2 lo, uint2 hi,
                                            float tx, float ty, float tz) {
    float2 l0 = __half22float2(*(__half2*)&lo.x);
    float2 l1 = __half22float2(*(__half2*)&lo.y);
    float2 h0 = __half22float2(*(__half2*)&hi.x);
    float2 h1 = __half22float2(*(__half2*)&hi.y);
    float c00 = l0.x + tx * (l0.y - l0.x);
    float c01 = l1.x + tx * (l1.y - l1.x);
    float c10 = h0.x + tx * (h0.y - h0.x);
    float c11 = h1.x + tx * (h1.y - h1.x);
    float c0  = c00 + ty * (c01 - c00);
    float c1  = c10 + ty * (c11 - c10);
    return c0 + tz * (c1 - c0);
}

__device__ __forceinline__ float sample_contracted(const float* __restrict__ vol,
                                                   float ix, float iy, float iz) {
    float x0f = floorf(ix), y0f = floorf(iy), z0f = floorf(iz);
    float tx = ix - x0f, ty = iy - y0f, tz = iz - z0f;
    int xi = (int)x0f - WLO;
    int yi = (int)y0f - WLO;
    int zi = (int)z0f - WLO;

    if ((unsigned)xi <= WMAXI && (unsigned)yi <= WMAXI && (unsigned)zi <= WMAXI) {
        int k  = zi >> 1;
        int zp = zi & 1;
        int idx = (k * WS + yi) * WS + xi;
        uint4 Q = __ldg(g_quad + idx);
        uint2 lo, hi;
        if (zp) {
            // z1 = next z-pair's even layer: low 8B of entry idx + WS*WS.
            uint2 F = __ldg((const uint2*)(g_quad + idx + WS * WS));
            lo = make_uint2(Q.z, Q.w);
            hi = F;
        } else {
            lo = make_uint2(Q.x, Q.y);
            hi = make_uint2(Q.z, Q.w);
        }
        return lerp_quads(lo, hi, tx, ty, tz);
    }
    // Outside the cached window (never for this input): exact fp32 path.
    return sample_fp32(vol, ix, iy, iz);
}

__global__ void __launch_bounds__(256)
sample_kernel(const float4* __restrict__ xyz,
              const float* __restrict__ vol,
              const float* __restrict__ aabb,
              const int*   __restrict__ cspace,
              float* __restrict__ out,
              int n) {
    int base = (blockIdx.x * blockDim.x + threadIdx.x) * 2;
    if (base >= n) return;

    float a0x = __ldg(aabb + 0), a0y = __ldg(aabb + 1), a0z = __ldg(aabb + 2);
    float a1x = __ldg(aabb + 3), a1y = __ldg(aabb + 4), a1z = __ldg(aabb + 5);
    float igx = 2.0f / (a1x - a0x);
    float igy = 2.0f / (a1y - a0y);
    float igz = 2.0f / (a1z - a0z);
    int cs = __ldg(cspace);

    bool has1 = (base + 1) < n;
    float4 pA = __ldg(xyz + base);
    float4 pB = has1 ? __ldg(xyz + base + 1) : pA;

    const float half_span = 0.5f * (DHW - 1);

    #pragma unroll
    for (int kk = 0; kk < 2; kk++) {
        int i = base + kk;
        if (kk == 1 && !has1) break;
        float4 p = (kk == 0) ? pA : pB;

        float cx = (p.x - a0x) * igx - 1.0f;
        float cy = (p.y - a0y) * igy - 1.0f;
        float cz = (p.z - a0z) * igz - 1.0f;

        float r;
        if (cs != 0) {
            float dist = fmaxf(fabsf(cx), fmaxf(fabsf(cy), fabsf(cz))) + 1e-8f;
            float scale = (dist > 1.0f) ? (2.0f - 1.0f / dist) : dist;
            float m = scale * 0.5f / dist;
            cx *= m; cy *= m; cz *= m;
            r = sample_contracted(vol,
                                  (cx + 1.0f) * half_span,
                                  (cy + 1.0f) * half_span,
                                  (cz + 1.0f) * half_span);
        } else {
            r = sample_fp32(vol,
                            (cx + 1.0f) * half_span,
                            (cy + 1.0f) * half_span,
                            (cz + 1.0f) * half_span);
        }
        out[i] = r;
    }
}

extern "C" void kernel_launch(void* const* d_in, const int* in_sizes, int n_in,
                              void* d_out, int out_size) {
    const float4* xyz  = (const float4*)d_in[0];
    const float*  vol  = (const float*)d_in[1];
    const float*  aabb = (const float*)d_in[2];
    const int*    cs   = (const int*)d_in[3];
    float* out = (float*)d_out;
    int n = out_size;

    convert_kernel<<<(CONV_TOTAL + 255) / 256, 256>>>(vol);

    int threads = 256;
    int pts_per_blk = threads * 2;
    int blocks = (n + pts_per_blk - 1) / pts_per_blk;
    sample_kernel<<<blocks, threads>>>(xyz, vol, aabb, cs, out, n);
}

// round 7
// speedup vs baseline: 2.0643x; 1.0103x over previous
#include <cuda_runtime.h>
#include <cuda_fp16.h>
#include <cstdint>

#define DHW 256

// Windowed quad table. Contracted coords for this problem satisfy
// |coord| <= 0.625 -> grid indices in [47.8, 207.2]; window [44, 211] covers
// it with margin. Any index outside the window takes the exact fp32 fallback.
#define WLO 44
#define WS  168
#define WK  (WS / 2)
#define WMAXI (WS - 2)

// Entry (k, yi, xi) packs the 8 trilinear corners of base (x, y, z=2k+WLO):
//  .x=(v[z][y][x],v[z][y][x+1]) .y=(v[z][y+1][x],v[z][y+1][x+1])
//  .z=(v[z+1][y][x],...)        .w=(v[z+1][y+1][x],...)        all fp16.
// 84*168*168*16B = 37.9 MB -> fully L2-resident.
__device__ uint4 g_quad[WK * WS * WS];

#define CONV_XG (WS / 4)
#define CONV_TOTAL (WK * WS * CONV_XG)

__global__ void __launch_bounds__(256)
convert_kernel(const float* __restrict__ vol) {
    int t = blockIdx.x * blockDim.x + threadIdx.x;
    if (t >= CONV_TOTAL) return;
    int xg   = t % CONV_XG;
    int rest = t / CONV_XG;
    int yi   = rest % WS;
    int k    = rest / WS;

    int x = WLO + (xg << 2);
    int y = WLO + yi;
    int z = WLO + (k << 1);

    const float* r00 = vol + ((z << 16) | (y << 8) | x);
    const float* r01 = r00 + 256;
    const float* r10 = r00 + 65536;
    const float* r11 = r10 + 256;

    float4 a0 = *(const float4*)r00;  float a0e = __ldg(r00 + 4);
    float4 a1 = *(const float4*)r01;  float a1e = __ldg(r01 + 4);
    float4 b0 = *(const float4*)r10;  float b0e = __ldg(r10 + 4);
    float4 b1 = *(const float4*)r11;  float b1e = __ldg(r11 + 4);

    float A0[5] = {a0.x, a0.y, a0.z, a0.w, a0e};
    float A1[5] = {a1.x, a1.y, a1.z, a1.w, a1e};
    float B0[5] = {b0.x, b0.y, b0.z, b0.w, b0e};
    float B1[5] = {b1.x, b1.y, b1.z, b1.w, b1e};

    uint4* dst = g_quad + ((k * WS + yi) * WS + (xg << 2));
    #pragma unroll
    for (int j = 0; j < 4; j++) {
        __half2 e0 = __floats2half2_rn(A0[j], A0[j + 1]);
        __half2 e1 = __floats2half2_rn(A1[j], A1[j + 1]);
        __half2 f0 = __floats2half2_rn(B0[j], B0[j + 1]);
        __half2 f1 = __floats2half2_rn(B1[j], B1[j + 1]);
        uint4 w;
        w.x = *(unsigned*)&e0; w.y = *(unsigned*)&e1;
        w.z = *(unsigned*)&f0; w.w = *(unsigned*)&f1;
        dst[j] = w;
    }
}

__device__ __forceinline__ float gather(const float* __restrict__ vol,
                                        int z, int y, int x) {
    if ((unsigned)z < (unsigned)DHW &&
        (unsigned)y < (unsigned)DHW &&
        (unsigned)x < (unsigned)DHW) {
        return __ldg(vol + ((z << 16) | (y << 8) | x));
    }
    return 0.0f;
}

__device__ __forceinline__ float sample_fp32(const float* __restrict__ vol,
                                             float ix, float iy, float iz) {
    float x0f = floorf(ix), y0f = floorf(iy), z0f = floorf(iz);
    float tx = ix - x0f, ty = iy - y0f, tz = iz - z0f;
    int x0 = (int)x0f, y0 = (int)y0f, z0 = (int)z0f;
    float v000 = gather(vol, z0, y0, x0);
    float v001 = gather(vol, z0, y0, x0 + 1);
    float v010 = gather(vol, z0, y0 + 1, x0);
    float v011 = gather(vol, z0, y0 + 1, x0 + 1);
    float v100 = gather(vol, z0 + 1, y0, x0);
    float v101 = gather(vol, z0 + 1, y0, x0 + 1);
    float v110 = gather(vol, z0 + 1, y0 + 1, x0);
    float v111 = gather(vol, z0 + 1, y0 + 1, x0 + 1);
    float c00 = v000 + tx * (v001 - v000);
    float c01 = v010 + tx * (v011 - v010);
    float c10 = v100 + tx * (v101 - v100);
    float c11 = v110 + tx * (v111 - v110);
    float c0  = c00 + ty * (c01 - c00);
    float c1  = c10 + ty * (c11 - c10);
    return c0 + tz * (c1 - c0);
}

struct PState {
    float tx, ty, tz;
    int idx;        // quad index, -1 -> fallback
    int zp;
    float ix, iy, iz;
};

__global__ void __launch_bounds__(256)
sample_kernel(const float4* __restrict__ xyz,
              const float* __restrict__ vol,
              const float* __restrict__ aabb,
              const int*   __restrict__ cspace,
              float* __restrict__ out,
              int n) {
    int base = (blockIdx.x * blockDim.x + threadIdx.x) * 4;
    if (base >= n) return;
    bool full = (base + 4) <= n;

    float a0x = __ldg(aabb + 0), a0y = __ldg(aabb + 1), a0z = __ldg(aabb + 2);
    float a1x = __ldg(aabb + 3), a1y = __ldg(aabb + 4), a1z = __ldg(aabb + 5);
    float igx = 2.0f / (a1x - a0x);
    float igy = 2.0f / (a1y - a0y);
    float igz = 2.0f / (a1z - a0z);
    int cs = __ldg(cspace);
    const float half_span = 0.5f * (DHW - 1);

    // Phase 1: load points (streaming; touched once).
    float4 p[4];
    #pragma unroll
    for (int j = 0; j < 4; j++) {
        int i = base + j;
        p[j] = (i < n) ? __ldcs(xyz + i) : make_float4(0.f, 0.f, 0.f, 0.f);
    }

    // Phase 2: coords.
    PState s[4];
    #pragma unroll
    for (int j = 0; j < 4; j++) {
        float cx = (p[j].x - a0x) * igx - 1.0f;
        float cy = (p[j].y - a0y) * igy - 1.0f;
        float cz = (p[j].z - a0z) * igz - 1.0f;
        if (cs != 0) {
            float dist = fmaxf(fabsf(cx), fmaxf(fabsf(cy), fabsf(cz))) + 1e-8f;
            float scale = (dist > 1.0f) ? (2.0f - 1.0f / dist) : dist;
            float m = scale * 0.5f / dist;
            cx *= m; cy *= m; cz *= m;
        }
        float ix = (cx + 1.0f) * half_span;
        float iy = (cy + 1.0f) * half_span;
        float iz = (cz + 1.0f) * half_span;
        float x0f = floorf(ix), y0f = floorf(iy), z0f = floorf(iz);
        s[j].tx = ix - x0f; s[j].ty = iy - y0f; s[j].tz = iz - z0f;
        s[j].ix = ix; s[j].iy = iy; s[j].iz = iz;
        int xi = (int)x0f - WLO;
        int yi = (int)y0f - WLO;
        int zi = (int)z0f - WLO;
        if (cs != 0 &&
            (unsigned)xi <= WMAXI && (unsigned)yi <= WMAXI && (unsigned)zi <= WMAXI) {
            s[j].zp  = zi & 1;
            s[j].idx = ((zi >> 1) * WS + yi) * WS + xi;
        } else {
            s[j].idx = -1;
        }
    }

    // Phase 3: issue all main 16B gathers back-to-back (MLP).
    uint4 Q[4];
    #pragma unroll
    for (int j = 0; j < 4; j++)
        Q[j] = (s[j].idx >= 0) ? __ldg(g_quad + s[j].idx)
                               : make_uint4(0u, 0u, 0u, 0u);

    // Phase 4: z-odd fixups (predicated; ~half the lanes per point).
    uint2 F[4];
    #pragma unroll
    for (int j = 0; j < 4; j++)
        F[j] = (s[j].idx >= 0 && s[j].zp)
             ? __ldg((const uint2*)(g_quad + s[j].idx + WS * WS))
             : make_uint2(0u, 0u);

    // Phase 5: lerp + store.
    float r[4];
    #pragma unroll
    for (int j = 0; j < 4; j++) {
        if (s[j].idx >= 0) {
            uint2 lo = s[j].zp ? make_uint2(Q[j].z, Q[j].w) : make_uint2(Q[j].x, Q[j].y);
            uint2 hi = s[j].zp ? F[j]                       : make_uint2(Q[j].z, Q[j].w);
            float2 l0 = __half22float2(*(__half2*)&lo.x);
            float2 l1 = __half22float2(*(__half2*)&lo.y);
            float2 h0 = __half22float2(*(__half2*)&hi.x);
            float2 h1 = __half22float2(*(__half2*)&hi.y);
            float c00 = l0.x + s[j].tx * (l0.y - l0.x);
            float c01 = l1.x + s[j].tx * (l1.y - l1.x);
            float c10 = h0.x + s[j].tx * (h0.y - h0.x);
            float c11 = h1.x + s[j].tx * (h1.y - h1.x);
            float c0  = c00 + s[j].ty * (c01 - c00);
            float c1  = c10 + s[j].ty * (c11 - c10);
            r[j] = c0 + s[j].tz * (c1 - c0);
        } else {
            r[j] = sample_fp32(vol, s[j].ix, s[j].iy, s[j].iz);
        }
    }

    if (full) {
        __stcs((float4*)(out + base), make_float4(r[0], r[1], r[2], r[3]));
    } else {
        #pragma unroll
        for (int j = 0; j < 4; j++)
            if (base + j < n) out[base + j] = r[j];
    }
}

extern "C" void kernel_launch(void* const* d_in, const int* in_sizes, int n_in,
                              void* d_out, int out_size) {
    const float4* xyz  = (const float4*)d_in[0];
    const float*  vol  = (const float*)d_in[1];
    const float*  aabb = (const float*)d_in[2];
    const int*    cs   = (const int*)d_in[3];
    float* out = (float*)d_out;
    int n = out_size;

    convert_kernel<<<(CONV_TOTAL + 255) / 256, 256>>>(vol);

    int threads = 256;
    int pts_per_blk = threads * 4;
    int blocks = (n + pts_per_blk - 1) / pts_per_blk;
    sample_kernel<<<blocks, threads>>>(xyz, vol, aabb, cs, out, n);
}